// round 16
// baseline (speedup 1.0000x reference)
#include <cuda_runtime.h>
#include <cstdint>

// Problem constants
#define B_    512
#define P_    65536
#define NOUT_ 512
#define COUT_ 4
#define NCLS_ 10

// R16: FOUR independent pipelines per SM. Grid 592 = 8 row-groups (64 rows)
// x 74 px-groups; 256-thread blocks, 4 blocks/SM. Small 32-px tiles, DEPTH=3
// cp.async pipeline per block. dram__cycles_active has been pinned at ~40%
// across R9-R15 (never saturated): single wide convoys leave the memory
// system idle between tile bursts; 4 staggered pipelines keep demand up.
#define RGS      8
#define RROWS    64
#define PGS      74
#define GRIDM    (RGS * PGS)          // 592
#define TILE_P   32
#define TILES_RG 2048                 // 65536 px / 32
#define XSTR     36                   // floats/row in smem (pad 4: conflict-free)
#define WPAD     12
#define DEPTH    3

#define XBUF_FLOATS (RROWS * XSTR)                     // 2304
#define XS_BYTES    (DEPTH * XBUF_FLOATS * 4)          // 27648
#define WSM_BYTES   (NOUT_ * WPAD * 4)                 // 24576
#define SEGB_BYTES  (DEPTH * TILE_P * 4)               // 384
#define BRED_BYTES  384                                // 8x10 warp beff + bsm + pad
#define SMEM_TOTAL  (XS_BYTES + WSM_BYTES + SEGB_BYTES + BRED_BYTES)  // 52992

// Scratch (allocation-free)
__device__ float g_partial[PGS * B_ * NCLS_];   // [74][512][10], 1.5MB
__device__ int   g_cnt[RGS];                    // arrival counters (reset by finalizer)

__device__ __forceinline__ uint32_t smem_u32(const void* p) {
    return (uint32_t)__cvta_generic_to_shared(p);
}
__device__ __forceinline__ void cp16(uint32_t smem, const void* gmem) {
    asm volatile("cp.async.cg.shared.global [%0], [%1], 16;" :: "r"(smem), "l"(gmem));
}
__device__ __forceinline__ unsigned long long packf2(float v) {
    unsigned long long r;
    asm("mov.b64 %0, {%1, %1};" : "=l"(r) : "f"(v));
    return r;
}
#define FMA2(acc, xv, wv) \
    asm("fma.rn.f32x2 %0, %1, %2, %0;" : "+l"(acc) : "l"(xv), "l"(wv))

// ---------------------------------------------------------------------------
__global__ void __launch_bounds__(256, 4)
fused_main_k(const float* __restrict__ x, const int* __restrict__ seg,
             const float* __restrict__ W_fgl, const float* __restrict__ b_fgl,
             const float* __restrict__ W_fc, const float* __restrict__ b_fc,
             float* __restrict__ out) {
    extern __shared__ __align__(16) char dynsmem[];
    float* xs   = (float*)dynsmem;                                   // [3][2304]
    float* wsm  = (float*)(dynsmem + XS_BYTES);                      // [512*12]
    int*   segb = (int*)(dynsmem + XS_BYTES + WSM_BYTES);            // [3][32]
    float* bred = (float*)(dynsmem + XS_BYTES + WSM_BYTES + SEGB_BYTES); // [8][10]
    float* bsm  = bred + 8 * NCLS_;                                  // [10]

    const int t    = threadIdx.x;
    const int warp = t >> 5;                // 0..7
    const int lane = t & 31;
    const int g    = blockIdx.x / PGS;      // row-group (0..7)
    const int pg   = blockIdx.x % PGS;      // px-group  (0..73)
    const int tStart = (pg * TILES_RG) / PGS;
    const int nT     = ((pg + 1) * TILES_RG) / PGS - tStart;   // 27 or 28

    const float* xbase = x + (size_t)(g * RROWS) * P_;

    auto stage = [&](int ft) {
        int buf  = ft % DEPTH;
        int pOff = (tStart + ft) * TILE_P;
        uint32_t xsb = smem_u32(xs + buf * XBUF_FLOATS);
#pragma unroll
        for (int r = 0; r < 2; r++) {          // 512 float4 over 256 threads
            int f   = r * 256 + t;
            int row = f >> 3;                  // 8 float4 per row (128B line)
            int c4  = (f & 7) << 2;
            cp16(xsb + (uint32_t)(row * XSTR + c4) * 4,
                 xbase + (size_t)row * P_ + pOff + c4);
        }
        if (t < 8) cp16(smem_u32(segb + buf * TILE_P) + t * 16, seg + pOff + t * 4);
    };

    // Prologue: 2 tiles in flight, then build Weff + beff (overlapped with DMA).
    stage(0); asm volatile("cp.async.commit_group;");
    stage(1); asm volatile("cp.async.commit_group;");
    {
        float locb[NCLS_];
#pragma unroll
        for (int k = 0; k < NCLS_; k++) locb[k] = 0.f;
#pragma unroll
        for (int jj = 0; jj < 2; jj++) {       // 512 regions over 256 threads
            int j = t + jj * 256;
            float w[NCLS_];
#pragma unroll
            for (int k = 0; k < NCLS_; k++) w[k] = 0.f;
#pragma unroll
            for (int c = 0; c < COUT_; c++) {
                int r = c * NOUT_ + j;
                float a  = W_fgl[r];
                float bb = b_fgl[r];
                const float* wf = W_fc + r * NCLS_;
#pragma unroll
                for (int k = 0; k < NCLS_; k++) {
                    float wv = wf[k];
                    w[k]    += a * wv;
                    locb[k] += bb * wv;
                }
            }
#pragma unroll
            for (int k = 0; k < NCLS_; k++) wsm[j * WPAD + k] = w[k];
        }
#pragma unroll
        for (int off = 16; off >= 1; off >>= 1)
#pragma unroll
            for (int k = 0; k < NCLS_; k++)
                locb[k] += __shfl_xor_sync(0xffffffffu, locb[k], off);
        if (lane == 0)
#pragma unroll
            for (int k = 0; k < NCLS_; k++) bred[warp * NCLS_ + k] = locb[k];
    }
    // (first loop iteration's __syncthreads orders wsm/bred before reads)

    unsigned long long accA[5], accB[5];       // f32x2, rows lane / lane+32
#pragma unroll
    for (int q = 0; q < 5; q++) { accA[q] = 0ull; accB[q] = 0ull; }

    auto compute = [&](int buf) {
        // warp handles px [warp*4, warp*4+4); lane rows: lane, lane+32
        const float* xb = &xs[buf * XBUF_FLOATS + lane * XSTR + warp * 4];
        float4 xa = *(const float4*)xb;                    // row = lane
        float4 xc = *(const float4*)(xb + 32 * XSTR);      // row = lane+32
        int4 sid = *(const int4*)&segb[buf * TILE_P + warp * 4];   // broadcast
#pragma unroll
        for (int j = 0; j < 4; j++) {
            int   id  = (j == 0) ? sid.x : (j == 1) ? sid.y : (j == 2) ? sid.z : sid.w;
            float xv0 = (j == 0) ? xa.x  : (j == 1) ? xa.y  : (j == 2) ? xa.z  : xa.w;
            float xv1 = (j == 0) ? xc.x  : (j == 1) ? xc.y  : (j == 2) ? xc.z  : xc.w;
            const unsigned long long* wrow =
                (const unsigned long long*)&wsm[id * WPAD];
            ulonglong2 wab = *(const ulonglong2*)(wrow);      // k0..3 (broadcast)
            ulonglong2 wcd = *(const ulonglong2*)(wrow + 2);  // k4..7
            unsigned long long we = wrow[4];                   // k8..9
            unsigned long long xp0 = packf2(xv0);
            unsigned long long xp1 = packf2(xv1);
            FMA2(accA[0], xp0, wab.x);  FMA2(accB[0], xp1, wab.x);
            FMA2(accA[1], xp0, wab.y);  FMA2(accB[1], xp1, wab.y);
            FMA2(accA[2], xp0, wcd.x);  FMA2(accB[2], xp1, wcd.x);
            FMA2(accA[3], xp0, wcd.y);  FMA2(accB[3], xp1, wcd.y);
            FMA2(accA[4], xp0, we);     FMA2(accB[4], xp1, we);
        }
    };

#pragma unroll 1
    for (int ft = 0; ft < nT; ft++) {
        asm volatile("cp.async.wait_group 1;");   // tile ft arrived
        __syncthreads();                          // compute(ft-1) done everywhere
        if (ft + 2 < nT) stage(ft + 2);           // -> buf (ft-1)%3, safe
        asm volatile("cp.async.commit_group;");   // empty at tail: uniform count
        compute(ft % DEPTH);
    }
    __syncthreads();   // all computes done; xs reusable as reduction space

    // Epilogue: 8 warp partials [8][64 rows][10] in xs, tree to slot 0.
    float* red = xs;                                     // 5120 floats needed
#pragma unroll
    for (int q = 0; q < 5; q++) {
        float lo, hi;
        asm("mov.b64 {%0,%1}, %2;" : "=f"(lo), "=f"(hi) : "l"(accA[q]));
        red[(warp * RROWS + lane) * NCLS_ + 2 * q]     = lo;
        red[(warp * RROWS + lane) * NCLS_ + 2 * q + 1] = hi;
        asm("mov.b64 {%0,%1}, %2;" : "=f"(lo), "=f"(hi) : "l"(accB[q]));
        red[(warp * RROWS + lane + 32) * NCLS_ + 2 * q]     = lo;
        red[(warp * RROWS + lane + 32) * NCLS_ + 2 * q + 1] = hi;
    }
    __syncthreads();
#pragma unroll
    for (int off = 4; off >= 1; off >>= 1) {
        for (int i = t; i < off * RROWS * NCLS_; i += 256) {
            int slot = i / (RROWS * NCLS_);
            int rem  = i - slot * (RROWS * NCLS_);
            red[slot * RROWS * NCLS_ + rem] += red[(slot + off) * RROWS * NCLS_ + rem];
        }
        __syncthreads();
    }
    if (t < NCLS_) {            // bsm: 8 warp beff partials + b_fc (fixed order)
        float a0 = 0.f, a1 = 0.f;
#pragma unroll
        for (int i = 0; i < 8; i += 2) {
            a0 += bred[i * NCLS_ + t];
            a1 += bred[(i + 1) * NCLS_ + t];
        }
        bsm[t] = b_fc[t] + a0 + a1;
    }
    for (int i = t; i < RROWS * NCLS_; i += 256) {   // 640 entries
        g_partial[((size_t)pg * B_ + g * RROWS) * NCLS_ + i] = red[i];
    }
    __threadfence();            // release partials (all threads)
    __syncthreads();

    // Last block of this row-group finalizes (threadFenceReduction pattern).
    __shared__ int is_last;
    if (t == 0) {
        int old = atomicAdd(&g_cnt[g], 1);
        is_last = (old == PGS - 1);
    }
    __syncthreads();
    if (is_last) {
        __threadfence();        // acquire all 74 partials
        for (int i = t; i < RROWS * NCLS_; i += 256) {
            int n = g * RROWS + i / NCLS_;
            int k = i % NCLS_;
            float sum = bsm[k];
#pragma unroll
            for (int s = 0; s < PGS; s++)      // fixed order: deterministic
                sum += g_partial[((size_t)s * B_ + n) * NCLS_ + k];
            out[n * NCLS_ + k] = sum;
        }
        __syncthreads();
        if (t == 0) g_cnt[g] = 0;              // reset for next (graph) launch
    }
}

// ---------------------------------------------------------------------------
extern "C" void kernel_launch(void* const* d_in, const int* in_sizes, int n_in,
                              void* d_out, int out_size) {
    const float* x     = (const float*)d_in[0];   // [512, 65536]
    const float* W_fgl = (const float*)d_in[1];   // [4, 512]
    const float* b_fgl = (const float*)d_in[2];   // [4, 512]
    const float* W_fc  = (const float*)d_in[3];   // [2048, 10]
    const float* b_fc  = (const float*)d_in[4];   // [10]
    const int*   seg   = (const int*)d_in[5];     // [65536]
    float* out = (float*)d_out;                   // [512, 10]

    cudaFuncSetAttribute(fused_main_k,
                         cudaFuncAttributeMaxDynamicSharedMemorySize, SMEM_TOTAL);

    fused_main_k<<<GRIDM, 256, SMEM_TOTAL>>>(x, seg, W_fgl, b_fgl, W_fc, b_fc, out);
    (void)in_sizes; (void)n_in; (void)out_size;
}

// round 17
// speedup vs baseline: 1.2170x; 1.2170x over previous
#include <cuda_runtime.h>
#include <cuda.h>
#include <cstdint>
#include <cstring>

// Problem constants
#define B_    512
#define P_    65536
#define NOUT_ 512
#define COUT_ 4
#define NCLS_ 10

// R17: TMA-2D staging. Grid 148 = 4 row-groups (128 rows) x 37 px-groups,
// 1 block/SM. Tile = 32 px x 128 rows = 16KB, fetched by ONE
// cp.async.bulk.tensor.2d (box {32,128}, SW128) into a 12-deep smem ring.
// Every cp.async variant (R9-R16) capped at ~3.3TB/s; TMA bypasses the
// per-thread LSU request path entirely.
#define RGS      4
#define RROWS    128
#define PGS      37
#define GRIDM    (RGS * PGS)          // 148
#define TILE_P   32
#define TILES_RG 2048
#define DEPTH    12
#define WPAD     12
#define TILE_BYTES (RROWS * TILE_P * 4)                // 16384

#define XS_BYTES   (DEPTH * TILE_BYTES)                // 196608
#define WSM_OFF    XS_BYTES
#define WSM_BYTES  (NOUT_ * WPAD * 4)                  // 24576
#define BRED_OFF   (WSM_OFF + WSM_BYTES)               // 221184
#define BRED_BYTES 704
#define MBAR_OFF   (BRED_OFF + BRED_BYTES)             // 221888 (8B aligned)
#define SMEM_TOTAL (MBAR_OFF + DEPTH * 8)              // 221984 <= 232448

// Scratch (allocation-free)
__device__ float g_partial[PGS * B_ * NCLS_];   // [37][512][10]
__device__ int   g_cnt[RGS];                    // arrival counters (reset by finalizer)

__device__ __forceinline__ uint32_t smem_u32(const void* p) {
    return (uint32_t)__cvta_generic_to_shared(p);
}
__device__ __forceinline__ unsigned long long packf2(float v) {
    unsigned long long r;
    asm("mov.b64 %0, {%1, %1};" : "=l"(r) : "f"(v));
    return r;
}
#define FMA2(acc, xv, wv) \
    asm("fma.rn.f32x2 %0, %1, %2, %0;" : "+l"(acc) : "l"(xv), "l"(wv))

#define MBAR_INIT(addr, cnt) \
    asm volatile("mbarrier.init.shared.b64 [%0], %1;" :: "r"(addr), "r"(cnt) : "memory")
#define MBAR_EXPECT_TX(addr, tx) \
    asm volatile("mbarrier.arrive.expect_tx.shared.b64 _, [%0], %1;" :: "r"(addr), "r"(tx) : "memory")
#define MBAR_WAIT(addr, ph) do {                                                  \
    asm volatile(                                                                 \
        "{\n\t.reg .pred P1;\n\t"                                                 \
        "WAIT_%=:\n\t"                                                            \
        "mbarrier.try_wait.parity.acquire.cta.shared::cta.b64 P1, [%0], %1, 0x989680;\n\t" \
        "@P1 bra.uni DONE_%=;\n\t"                                                \
        "bra.uni WAIT_%=;\n\t"                                                    \
        "DONE_%=:\n\t}"                                                           \
        :: "r"(addr), "r"(ph) : "memory");                                        \
} while (0)

// ---------------------------------------------------------------------------
__global__ void __launch_bounds__(512, 1)
fused_main_k(const __grid_constant__ CUtensorMap tmap,
             const int* __restrict__ seg,
             const float* __restrict__ W_fgl, const float* __restrict__ b_fgl,
             const float* __restrict__ W_fc, const float* __restrict__ b_fc,
             float* __restrict__ out) {
    extern __shared__ __align__(1024) char dynsmem[];
    float* wsm  = (float*)(dynsmem + WSM_OFF);       // [512*12] Weff table
    float* bred = (float*)(dynsmem + BRED_OFF);      // [16][10]
    float* bsm  = bred + 16 * NCLS_;                 // [10]
    const uint32_t xs_u  = smem_u32(dynsmem);
    const uint32_t mbar0 = smem_u32(dynsmem + MBAR_OFF);

    const int t    = threadIdx.x;
    const int warp = t >> 5;                // 0..15
    const int lane = t & 31;
    const int g    = blockIdx.x / PGS;      // row-group (0..3)
    const int pg   = blockIdx.x % PGS;      // px-group  (0..36)
    const int tStart = (pg * TILES_RG) / PGS;
    const int nT     = ((pg + 1) * TILES_RG) / PGS - tStart;   // 55 or 56

    // mbarrier init (arrive count 1 = the expect_tx arrive by t0).
    if (t == 0) {
#pragma unroll
        for (int i = 0; i < DEPTH; i++) MBAR_INIT(mbar0 + i * 8, 1);
        asm volatile("fence.proxy.async.shared::cta;" ::: "memory");
    }
    __syncthreads();

    auto stage = [&](int ft) {   // t==0 only: one TMA per 16KB tile
        int buf = ft % DEPTH;
        uint32_t mb = mbar0 + buf * 8;
        MBAR_EXPECT_TX(mb, TILE_BYTES);
        int cx = (tStart + ft) * TILE_P;
        int cy = g * RROWS;
        asm volatile(
            "cp.async.bulk.tensor.2d.shared::cta.global.tile.mbarrier::complete_tx::bytes "
            "[%0], [%1, {%2, %3}], [%4];"
            :: "r"(xs_u + (uint32_t)buf * TILE_BYTES), "l"(&tmap),
               "r"(cx), "r"(cy), "r"(mb) : "memory");
    };

    // Prologue: fill DEPTH-1 ring slots, then build Weff + beff (overlapped).
    if (t == 0) {
        int nPro = (DEPTH - 1 < nT) ? DEPTH - 1 : nT;
        for (int i = 0; i < nPro; i++) stage(i);
    }
    {
        int j = t;                              // 512 threads == 512 regions
        float w[NCLS_], locb[NCLS_];
#pragma unroll
        for (int k = 0; k < NCLS_; k++) { w[k] = 0.f; locb[k] = 0.f; }
#pragma unroll
        for (int c = 0; c < COUT_; c++) {
            int r = c * NOUT_ + j;
            float a  = W_fgl[r];
            float bb = b_fgl[r];
            const float* wf = W_fc + r * NCLS_;
#pragma unroll
            for (int k = 0; k < NCLS_; k++) {
                float wv = wf[k];
                w[k]    += a * wv;
                locb[k] += bb * wv;
            }
        }
#pragma unroll
        for (int k = 0; k < NCLS_; k++) wsm[j * WPAD + k] = w[k];
#pragma unroll
        for (int off = 16; off >= 1; off >>= 1)
#pragma unroll
            for (int k = 0; k < NCLS_; k++)
                locb[k] += __shfl_xor_sync(0xffffffffu, locb[k], off);
        if (lane == 0)
#pragma unroll
            for (int k = 0; k < NCLS_; k++) bred[warp * NCLS_ + k] = locb[k];
    }
    // (loop iteration 0's __syncthreads orders wsm/bred before any reads)

    unsigned long long acc[4][5];   // [row-set][class-pair] f32x2
#pragma unroll
    for (int rs = 0; rs < 4; rs++)
#pragma unroll
        for (int q = 0; q < 5; q++) acc[rs][q] = 0ull;

    // Warp handles px pair (warp*2, warp*2+1); lane rows: lane,+32,+64,+96.
    auto compute = [&](int buf, int2 sid) {
        uint32_t xb = xs_u + (uint32_t)buf * TILE_BYTES;
        float xlo[4], xhi[4];
#pragma unroll
        for (int rs = 0; rs < 4; rs++) {
            uint32_t byte = (uint32_t)(lane + rs * 32) * 128 + warp * 8;
            uint32_t sw   = byte ^ ((byte >> 3) & 0x70);   // SW128
            unsigned long long v;
            asm volatile("ld.shared.b64 %0, [%1];" : "=l"(v) : "r"(xb + sw));
            asm("mov.b64 {%0,%1}, %2;" : "=f"(xlo[rs]), "=f"(xhi[rs]) : "l"(v));
        }
#pragma unroll
        for (int j = 0; j < 2; j++) {
            int id = j ? sid.y : sid.x;
            const unsigned long long* wrow =
                (const unsigned long long*)&wsm[id * WPAD];
            ulonglong2 wab = *(const ulonglong2*)(wrow);      // k0..3 (broadcast)
            ulonglong2 wcd = *(const ulonglong2*)(wrow + 2);  // k4..7
            unsigned long long we = wrow[4];                   // k8..9
#pragma unroll
            for (int rs = 0; rs < 4; rs++) {
                unsigned long long xp = packf2(j ? xhi[rs] : xlo[rs]);
                FMA2(acc[rs][0], xp, wab.x);
                FMA2(acc[rs][1], xp, wab.y);
                FMA2(acc[rs][2], xp, wcd.x);
                FMA2(acc[rs][3], xp, wcd.y);
                FMA2(acc[rs][4], xp, we);
            }
        }
    };

    auto segld = [&](int ft) {   // warp-uniform address -> broadcast, L2-hot
        return *(const int2*)(seg + (tStart + ft) * TILE_P + warp * 2);
    };

    int2 sidCur = segld(0);
#pragma unroll 1
    for (int ft = 0; ft < nT; ft++) {
        int buf = ft % DEPTH;
        MBAR_WAIT(mbar0 + buf * 8, (ft / DEPTH) & 1);   // tile ft arrived
        __syncthreads();                                 // compute(ft-1) done everywhere
        if (t == 0 && ft + DEPTH - 1 < nT) stage(ft + DEPTH - 1);
        int2 sidNext = (ft + 1 < nT) ? segld(ft + 1) : sidCur;
        compute(buf, sidCur);
        sidCur = sidNext;
    }
    __syncthreads();   // all computes done; xs reusable as reduction space

    // Epilogue: reduce 16 warps' partials -> one block partial (fixed order).
    float* red = (float*)dynsmem;                        // 10240 floats used
#pragma unroll
    for (int rs = 0; rs < 4; rs++) {
        int row = lane + rs * 32;
        if (warp < 8) {
#pragma unroll
            for (int q = 0; q < 5; q++) {
                float lo, hi;
                asm("mov.b64 {%0,%1}, %2;" : "=f"(lo), "=f"(hi) : "l"(acc[rs][q]));
                red[(warp * RROWS + row) * NCLS_ + 2 * q]     = lo;
                red[(warp * RROWS + row) * NCLS_ + 2 * q + 1] = hi;
            }
        }
    }
    __syncthreads();
    if (warp >= 8) {
#pragma unroll
        for (int rs = 0; rs < 4; rs++) {
            int row = lane + rs * 32;
            float* dst = &red[((warp - 8) * RROWS + row) * NCLS_];
#pragma unroll
            for (int q = 0; q < 5; q++) {
                float lo, hi;
                asm("mov.b64 {%0,%1}, %2;" : "=f"(lo), "=f"(hi) : "l"(acc[rs][q]));
                dst[2 * q]     += lo;
                dst[2 * q + 1] += hi;
            }
        }
    }
    __syncthreads();
#pragma unroll
    for (int off = 4; off >= 1; off >>= 1) {
        for (int i = t; i < off * RROWS * NCLS_; i += 512) {
            int slot = i / (RROWS * NCLS_);
            int rem  = i - slot * (RROWS * NCLS_);
            red[slot * RROWS * NCLS_ + rem] += red[(slot + off) * RROWS * NCLS_ + rem];
        }
        __syncthreads();
    }
    if (t < NCLS_) {            // bsm: 16 warp beff partials + b_fc (fixed order)
        float a0 = 0.f, a1 = 0.f;
#pragma unroll
        for (int i = 0; i < 16; i += 2) {
            a0 += bred[i * NCLS_ + t];
            a1 += bred[(i + 1) * NCLS_ + t];
        }
        bsm[t] = b_fc[t] + a0 + a1;
    }
    for (int i = t; i < RROWS * NCLS_; i += 512) {   // 1280 entries
        g_partial[((size_t)pg * B_ + g * RROWS) * NCLS_ + i] = red[i];
    }
    __threadfence();            // release partials
    __syncthreads();

    // Last block of this row-group finalizes (threadFenceReduction pattern).
    __shared__ int is_last;
    if (t == 0) {
        int old = atomicAdd(&g_cnt[g], 1);
        is_last = (old == PGS - 1);
    }
    __syncthreads();
    if (is_last) {
        __threadfence();        // acquire all 37 partials
        for (int i = t; i < RROWS * NCLS_; i += 512) {
            int n = g * RROWS + i / NCLS_;
            int k = i % NCLS_;
            float sum = bsm[k];
#pragma unroll
            for (int s = 0; s < PGS; s++)      // fixed order: deterministic
                sum += g_partial[((size_t)s * B_ + n) * NCLS_ + k];
            out[n * NCLS_ + k] = sum;
        }
        __syncthreads();
        if (t == 0) g_cnt[g] = 0;              // reset for next (graph) launch
    }
}

// ---------------------------------------------------------------------------
typedef CUresult (*EncodeTiledFn)(
    CUtensorMap*, CUtensorMapDataType, cuuint32_t, void*,
    const cuuint64_t*, const cuuint64_t*, const cuuint32_t*, const cuuint32_t*,
    CUtensorMapInterleave, CUtensorMapSwizzle, CUtensorMapL2promotion,
    CUtensorMapFloatOOBfill);

extern "C" void kernel_launch(void* const* d_in, const int* in_sizes, int n_in,
                              void* d_out, int out_size) {
    const float* x     = (const float*)d_in[0];   // [512, 65536]
    const float* W_fgl = (const float*)d_in[1];   // [4, 512]
    const float* b_fgl = (const float*)d_in[2];   // [4, 512]
    const float* W_fc  = (const float*)d_in[3];   // [2048, 10]
    const float* b_fc  = (const float*)d_in[4];   // [10]
    const int*   seg   = (const int*)d_in[5];     // [65536]
    float* out = (float*)d_out;                   // [512, 10]

    cudaFuncSetAttribute(fused_main_k,
                         cudaFuncAttributeMaxDynamicSharedMemorySize, SMEM_TOTAL);

    // Build the 2D tensormap for x host-side (pure host work at capture time;
    // no allocations, no stream ops). Driver entry point via runtime API —
    // no -lcuda link dependency.
    void* fn = nullptr;
    cudaDriverEntryPointQueryResult qr;
    cudaGetDriverEntryPoint("cuTensorMapEncodeTiled", &fn,
                            cudaEnableDefault, &qr);
    CUtensorMap tmap;
    memset(&tmap, 0, sizeof(tmap));
    cuuint64_t dims[2]    = {P_, B_};
    cuuint64_t strides[1] = {(cuuint64_t)P_ * 4};   // row stride in bytes
    cuuint32_t box[2]     = {TILE_P, RROWS};        // 32 px x 128 rows
    cuuint32_t estr[2]    = {1, 1};
    ((EncodeTiledFn)fn)(&tmap, CU_TENSOR_MAP_DATA_TYPE_FLOAT32, 2,
                        (void*)x, dims, strides, box, estr,
                        CU_TENSOR_MAP_INTERLEAVE_NONE,
                        CU_TENSOR_MAP_SWIZZLE_128B,
                        CU_TENSOR_MAP_L2_PROMOTION_L2_128B,
                        CU_TENSOR_MAP_FLOAT_OOB_FILL_NONE);

    fused_main_k<<<GRIDM, 512, SMEM_TOTAL>>>(tmap, seg, W_fgl, b_fgl,
                                             W_fc, b_fc, out);
    (void)in_sizes; (void)n_in; (void)out_size;
}